// round 11
// baseline (speedup 1.0000x reference)
#include <cuda_runtime.h>

// Problem constants (fixed by the dataset shapes)
#define B_   32
#define NL_  13
#define L_   1024
#define D_   768
#define LCHUNKS_ 32
#define LCHUNK_  (L_ / LCHUNKS_)   // 32 rows per block
#define NT_  (D_ / 4)              // 192 threads

// ---------------------------------------------------------------------------
// Kernel A: zero the poisoned output (98 KB). Trivial; PDL producer so the
// fused kernel's epilogue reductions can be release-gated on it.
// ---------------------------------------------------------------------------
__global__ void zero_out_kernel(float* __restrict__ out)
{
    out[blockIdx.x * D_ + threadIdx.x] = 0.0f;
    asm volatile("griddepcontrol.launch_dependents;");
}

// ---------------------------------------------------------------------------
// Fused kernel: grid (32 chunks, 32 batches) = 1024 blocks (one wave),
// 192 threads (one float4 column group per thread).
//
// Phase 0: issue first 8 feature-row loads (pure input, no dependencies) --
//          ~24 MB of the stream enters the memory system at t=0.
// Phase 1: redundant per-block weight computation for this block's batch:
//          vq low words -> smem (8 KB, L2-hit after first touch per batch),
//          boundary flags, block-reduce num_runs, O(1) local walks for this
//          chunk's 32 rows (runs are ~always length 1: collision prob 1/320^2).
//          Entirely hidden under the phase-0 loads.
// Phase 2: stream remaining 24 rows (8-deep batched __ldcs LDG.128, proven
//          R7 schedule) weighted by smem weights.
// Phase 3: griddepcontrol.wait (zero kernel) + one red.global.v4.f32.
//
// Integer inputs are read through an int32 view with runtime-detected element
// stride (JAX silently downcasts int64->int32 without x64). lengths are in
// [512,1024] (never 0), so word[1]==0  <=>  little-endian int64 layout.
// vq values < 320 < 2^31, so low words fully determine equality either way.
// ---------------------------------------------------------------------------
__global__ void __launch_bounds__(NT_)
vq_fused_kernel(const float* __restrict__ feat,
                const int*   __restrict__ len32,
                const int*   __restrict__ vq32,
                float*       __restrict__ out)
{
    const int b  = blockIdx.y;
    const int lc = blockIdx.x;
    const int t  = threadIdx.x;     // 0..191
    const int lane = t & 31;
    const int warp = t >> 5;

    __shared__ int           s_v0[L_];
    __shared__ int           s_v1[L_];
    __shared__ unsigned char s_bnd[L_];
    __shared__ int           s_red[8];
    __shared__ float         s_w[LCHUNK_];
    __shared__ int           s_nr;

    // dtype detection (uniform)
    const int stride = (len32[1] == 0) ? 2 : 1;
    const int len    = len32[b * stride];

    const int l0 = lc * LCHUNK_;
    if (l0 >= len) return;          // whole chunk is zero-weight (uniform exit)

    const float4* __restrict__ fb = (const float4*)
        (feat + ((size_t)b * NL_ + (NL_ - 1)) * (size_t)(L_ * D_));
    float* ob = out + b * D_ + t * 4;

    // ---- Phase 0: prefetch first 8 rows (independent of everything) ----
    float4 f[8];
    #pragma unroll
    for (int k = 0; k < 8; ++k)
        f[k] = __ldcs(&fb[(size_t)(l0 + k) * NT_ + t]);

    // ---- Phase 1: weights for this batch (hidden under phase-0 loads) ----
    const int vbase = b * L_ * 2;
    #pragma unroll 2
    for (int idx = t; idx < L_; idx += NT_) {
        s_v0[idx] = vq32[(vbase + 2 * idx + 0) * stride];
        s_v1[idx] = vq32[(vbase + 2 * idx + 1) * stride];
    }
    __syncthreads();

    int cnt = 0;
    #pragma unroll 2
    for (int idx = t; idx < L_; idx += NT_) {
        bool bnd = (idx < len) &&
                   (idx == 0 || s_v0[idx] != s_v0[idx - 1]
                             || s_v1[idx] != s_v1[idx - 1]);
        s_bnd[idx] = bnd ? 1 : 0;
        cnt += bnd ? 1 : 0;
    }
    #pragma unroll
    for (int off = 16; off > 0; off >>= 1)
        cnt += __shfl_down_sync(0xffffffffu, cnt, off);
    if (lane == 0) s_red[warp] = cnt;
    __syncthreads();
    if (t == 0) {
        int tot = 0;
        #pragma unroll
        for (int w = 0; w < NT_ / 32; ++w) tot += s_red[w];
        s_nr = tot;
    }
    __syncthreads();

    if (t < LCHUNK_) {
        const int i = l0 + t;
        float wv = 0.0f;
        if (i < len) {
            int s = i;
            while (!s_bnd[s]) --s;               // expected 0 iterations
            int e = i + 1;
            while (e < len && !s_bnd[e]) ++e;    // expected 0 iterations
            wv = 1.0f / ((float)s_nr * (float)(e - s));
        }
        s_w[t] = wv;
    }
    __syncthreads();

    // ---- Phase 2: weighted accumulation ----
    float4 acc = make_float4(0.f, 0.f, 0.f, 0.f);

    #pragma unroll
    for (int k = 0; k < 8; ++k) {
        const float wl = s_w[k];
        acc.x = fmaf(wl, f[k].x, acc.x);
        acc.y = fmaf(wl, f[k].y, acc.y);
        acc.z = fmaf(wl, f[k].z, acc.z);
        acc.w = fmaf(wl, f[k].w, acc.w);
    }

    #pragma unroll
    for (int j = 8; j < LCHUNK_; j += 8) {
        float4 g[8];
        #pragma unroll
        for (int k = 0; k < 8; ++k)
            g[k] = __ldcs(&fb[(size_t)(l0 + j + k) * NT_ + t]);
        #pragma unroll
        for (int k = 0; k < 8; ++k) {
            const float wl = s_w[j + k];
            acc.x = fmaf(wl, g[k].x, acc.x);
            acc.y = fmaf(wl, g[k].y, acc.y);
            acc.z = fmaf(wl, g[k].z, acc.z);
            acc.w = fmaf(wl, g[k].w, acc.w);
        }
    }

    // ---- Phase 3: gated epilogue (zero kernel must have completed) ----
    asm volatile("griddepcontrol.wait;" ::: "memory");
    asm volatile("red.global.add.v4.f32 [%0], {%1, %2, %3, %4};"
                 :: "l"(ob), "f"(acc.x), "f"(acc.y), "f"(acc.z), "f"(acc.w)
                 : "memory");
}

// ---------------------------------------------------------------------------
extern "C" void kernel_launch(void* const* d_in, const int* in_sizes, int n_in,
                              void* d_out, int out_size)
{
    const float* feat  = (const float*)d_in[0];   // (B, NL, L, D) f32
    const int*   len32 = (const int*)d_in[1];     // (B,) i32 or i64 (detected)
    const int*   vq32  = (const int*)d_in[2];     // (B, L, 2) i32 or i64 (detected)
    float*       out   = (float*)d_out;           // (B, D) f32

    zero_out_kernel<<<B_, D_>>>(out);

    // Fused kernel with programmatic stream serialization (PDL): launches
    // while the zero kernel runs; only the epilogue red is gated.
    cudaLaunchConfig_t cfg = {};
    cfg.gridDim  = dim3(LCHUNKS_, B_);
    cfg.blockDim = dim3(NT_);
    cudaLaunchAttribute attr[1];
    attr[0].id = cudaLaunchAttributeProgrammaticStreamSerialization;
    attr[0].val.programmaticStreamSerializationAllowed = 1;
    cfg.attrs    = attr;
    cfg.numAttrs = 1;
    cudaLaunchKernelEx(&cfg, vq_fused_kernel, feat, len32, vq32, out);
}